// round 6
// baseline (speedup 1.0000x reference)
#include <cuda_runtime.h>
#include <cuda_bf16.h>

#define N_NODES 40000
#define N_EDGES 640000
#define D 128
#define NB 157  // ceil(40000/256) scan blocks

// ---------------- scratch (device globals, referenced by symbol only) ----------------
__device__ float g_h[N_NODES * D];        // GEMM output (per layer)
__device__ float g_y[N_NODES * D];        // layer-1 output
__device__ int   g_deg[N_NODES];          // degree histogram (by dst)
__device__ int   g_rowptr[N_NODES + 1];   // CSR row pointers
__device__ int   g_cursor[N_NODES];       // fill cursors
__device__ int   g_srcs[N_EDGES];         // CSR: src node per slot
__device__ float g_scale[N_EDGES];        // CSR: 1/edge_attr per slot
__device__ int   g_is32;                  // 1 if edge_index is int32, 0 if int64
__device__ int   g_bsum[NB];              // per-block degree sums
__device__ int   g_boff[NB];              // exclusive block offsets

// ---------------- init: zero degree histogram + detect edge_index dtype ----------------
__global__ __launch_bounds__(256) void init_kernel(const int* __restrict__ ei32) {
    int i = blockIdx.x * 256 + threadIdx.x;
    if (i < N_NODES) g_deg[i] = 0;
    if (blockIdx.x == 0) {
        int nz = 0;
        for (int s = threadIdx.x; s < 4096; s += 256)
            nz |= (ei32[2 * s + 1] != 0);
        nz = __syncthreads_or(nz);
        if (threadIdx.x == 0) g_is32 = nz;
    }
}

__device__ __forceinline__ int load_idx(const void* ei, int pos) {
    if (g_is32) return ((const int*)ei)[pos];
    return (int)((const long long*)ei)[pos];
}

__global__ void count_kernel(const void* __restrict__ ei) {
    int e = blockIdx.x * blockDim.x + threadIdx.x;
    if (e >= N_EDGES) return;
    int dst = load_idx(ei, N_EDGES + e);
    if ((unsigned)dst < (unsigned)N_NODES) atomicAdd(&g_deg[dst], 1);
}

// ---- scan phase 1: per-block sums ----
__global__ __launch_bounds__(256) void bsum_kernel() {
    int i = blockIdx.x * 256 + threadIdx.x;
    int v = (i < N_NODES) ? g_deg[i] : 0;
#pragma unroll
    for (int off = 16; off > 0; off >>= 1)
        v += __shfl_down_sync(0xffffffffu, v, off);
    __shared__ int ws[8];
    int wid = threadIdx.x >> 5, lane = threadIdx.x & 31;
    if (lane == 0) ws[wid] = v;
    __syncthreads();
    if (threadIdx.x == 0) {
        int s = 0;
#pragma unroll
        for (int w = 0; w < 8; w++) s += ws[w];
        g_bsum[blockIdx.x] = s;
    }
}

// ---- scan phase 2: exclusive scan of NB block sums ----
__global__ __launch_bounds__(256) void bscan_kernel() {
    int t = threadIdx.x;
    int lane = t & 31, wid = t >> 5;
    int v = (t < NB) ? g_bsum[t] : 0;
    int orig = v;
#pragma unroll
    for (int off = 1; off < 32; off <<= 1) {
        int u = __shfl_up_sync(0xffffffffu, v, off);
        if (lane >= off) v += u;
    }
    __shared__ int wsum[8];
    if (lane == 31) wsum[wid] = v;
    __syncthreads();
    if (wid == 0) {
        int s = (lane < 8) ? wsum[lane] : 0;
#pragma unroll
        for (int off = 1; off < 8; off <<= 1) {
            int u = __shfl_up_sync(0xffffffffu, s, off);
            if (lane >= off) s += u;
        }
        if (lane < 8) wsum[lane] = s;
    }
    __syncthreads();
    int incl = v + (wid > 0 ? wsum[wid - 1] : 0);
    if (t < NB) g_boff[t] = incl - orig;
}

// ---- scan phase 3: intra-block exclusive scan + write rowptr/cursor ----
__global__ __launch_bounds__(256) void rowptr_kernel() {
    int i = blockIdx.x * 256 + threadIdx.x;
    int lane = threadIdx.x & 31, wid = threadIdx.x >> 5;
    int v = (i < N_NODES) ? g_deg[i] : 0;
    int orig = v;
#pragma unroll
    for (int off = 1; off < 32; off <<= 1) {
        int u = __shfl_up_sync(0xffffffffu, v, off);
        if (lane >= off) v += u;
    }
    __shared__ int wsum[8];
    if (lane == 31) wsum[wid] = v;
    __syncthreads();
    if (wid == 0) {
        int s = (lane < 8) ? wsum[lane] : 0;
#pragma unroll
        for (int off = 1; off < 8; off <<= 1) {
            int u = __shfl_up_sync(0xffffffffu, s, off);
            if (lane >= off) s += u;
        }
        if (lane < 8) wsum[lane] = s;
    }
    __syncthreads();
    int incl = v + (wid > 0 ? wsum[wid - 1] : 0);
    int excl = incl - orig + g_boff[blockIdx.x];
    if (i < N_NODES) {
        g_rowptr[i] = excl;
        g_cursor[i] = excl;
        if (i == N_NODES - 1) g_rowptr[N_NODES] = excl + orig;
    }
}

__global__ void fill_kernel(const void* __restrict__ ei,
                            const float* __restrict__ ea) {
    int e = blockIdx.x * blockDim.x + threadIdx.x;
    if (e >= N_EDGES) return;
    int src = load_idx(ei, e);
    int dst = load_idx(ei, N_EDGES + e);
    if ((unsigned)dst >= (unsigned)N_NODES) return;
    if ((unsigned)src >= (unsigned)N_NODES) return;
    int pos = atomicAdd(&g_cursor[dst], 1);
    g_srcs[pos]  = src;
    g_scale[pos] = 1.0f / ea[e];
}

// ---------------- GEMM v2: g_h = X @ W^T via FFMA2, dup-A smem layout ----------------
// BM=64, BN=128, BK=16, 256 threads, 3 CTAs/SM.
// As_dup[k][2m]=As_dup[k][2m+1]=X[m][k] -> a-pairs via LDS.128, no movs.
// Thread tile 4 rows x 8 cols (4 col-pairs), acc2[4][4].
__global__ __launch_bounds__(256, 3) void gemm_nt_kernel(const float* __restrict__ x_ext,
                                                         const float* __restrict__ W,
                                                         int layer) {
    __shared__ __align__(16) float As_dup[16][128];  // 8 KB (64 rows duplicated)
    __shared__ __align__(16) float Bs[16][128];      // 8 KB
    const float* X = (layer == 0) ? x_ext : (const float*)g_y;
    const int block_row = blockIdx.x * 64;           // 625 blocks, exact
    const int tid  = threadIdx.x;
    const int w    = tid >> 5;
    const int lane = tid & 31;
    const int wr = w & 3;          // warp row group (16 rows each)
    const int wc = w >> 2;         // warp col group (64 cols each)
    const int lr = lane >> 3;      // lane row group (4 rows each)
    const int lc = lane & 7;       // lane col group (8 cols each)
    const int r0 = wr * 16 + lr * 4;   // thread rows r0..r0+3 (local)
    const int c0 = wc * 64 + lc * 8;   // thread cols c0..c0+7

    unsigned long long acc2[4][4];
#pragma unroll
    for (int i = 0; i < 4; i++)
#pragma unroll
        for (int j = 0; j < 4; j++) acc2[i][j] = 0ull;

    // loader mappings
    const int a_row = tid >> 2;          // 0..63
    const int a_kc  = (tid & 3) * 4;     // 0,4,8,12
    const int b_row = tid >> 1;          // 0..127
    const int b_kc  = (tid & 1) * 8;     // 0,8

    for (int k0 = 0; k0 < 128; k0 += 16) {
        // load X tile (64x16) -> As_dup, duplicated along m
        {
            float4 v = *reinterpret_cast<const float4*>(X + (size_t)(block_row + a_row) * D + k0 + a_kc);
            float2* p0 = reinterpret_cast<float2*>(&As_dup[a_kc + 0][2 * a_row]);
            float2* p1 = reinterpret_cast<float2*>(&As_dup[a_kc + 1][2 * a_row]);
            float2* p2 = reinterpret_cast<float2*>(&As_dup[a_kc + 2][2 * a_row]);
            float2* p3 = reinterpret_cast<float2*>(&As_dup[a_kc + 3][2 * a_row]);
            *p0 = make_float2(v.x, v.x);
            *p1 = make_float2(v.y, v.y);
            *p2 = make_float2(v.z, v.z);
            *p3 = make_float2(v.w, v.w);
        }
        // load W tile (128 n x 16 k) -> Bs[k][n]
        {
            float4 v0 = *reinterpret_cast<const float4*>(W + (size_t)b_row * D + k0 + b_kc);
            float4 v1 = *reinterpret_cast<const float4*>(W + (size_t)b_row * D + k0 + b_kc + 4);
            Bs[b_kc + 0][b_row] = v0.x; Bs[b_kc + 1][b_row] = v0.y;
            Bs[b_kc + 2][b_row] = v0.z; Bs[b_kc + 3][b_row] = v0.w;
            Bs[b_kc + 4][b_row] = v1.x; Bs[b_kc + 5][b_row] = v1.y;
            Bs[b_kc + 6][b_row] = v1.z; Bs[b_kc + 7][b_row] = v1.w;
        }
        __syncthreads();

#pragma unroll
        for (int k = 0; k < 16; k++) {
            // a: 4 duplicated pairs = 2x LDS.128
            ulonglong2 av0 = *reinterpret_cast<const ulonglong2*>(&As_dup[k][2 * r0]);
            ulonglong2 av1 = *reinterpret_cast<const ulonglong2*>(&As_dup[k][2 * r0 + 4]);
            // b: 4 natural col-pairs = 2x LDS.128
            ulonglong2 bv0 = *reinterpret_cast<const ulonglong2*>(&Bs[k][c0]);
            ulonglong2 bv1 = *reinterpret_cast<const ulonglong2*>(&Bs[k][c0 + 4]);
            unsigned long long a2[4] = {av0.x, av0.y, av1.x, av1.y};
            unsigned long long b2[4] = {bv0.x, bv0.y, bv1.x, bv1.y};
#pragma unroll
            for (int i = 0; i < 4; i++)
#pragma unroll
                for (int j = 0; j < 4; j++)
                    asm("fma.rn.f32x2 %0, %1, %2, %0;" : "+l"(acc2[i][j]) : "l"(a2[i]), "l"(b2[j]));
        }
        __syncthreads();
    }

#pragma unroll
    for (int i = 0; i < 4; i++) {
        int gr = block_row + r0 + i;
        float o[8];
#pragma unroll
        for (int j = 0; j < 4; j++) {
            unsigned int lo, hi;
            asm("mov.b64 {%0, %1}, %2;" : "=r"(lo), "=r"(hi) : "l"(acc2[i][j]));
            o[2 * j]     = __uint_as_float(lo);
            o[2 * j + 1] = __uint_as_float(hi);
        }
        float4* op = reinterpret_cast<float4*>((float*)g_h + (size_t)gr * D + c0);
        op[0] = make_float4(o[0], o[1], o[2], o[3]);
        op[1] = make_float4(o[4], o[5], o[6], o[7]);
    }
}

// ---------------- aggregate: dst[n] = relu( sum_{e in CSR[n]} g_h[src_e]*scale_e + bias ) ----------------
__global__ __launch_bounds__(256) void agg_kernel(const float* __restrict__ bias,
                                                  float* __restrict__ out_ext,
                                                  int layer) {
    int warp = (blockIdx.x * blockDim.x + threadIdx.x) >> 5;
    int lane = threadIdx.x & 31;
    if (warp >= N_NODES) return;
    const float* H = (const float*)g_h;
    float* outp = (layer == 0) ? (float*)g_y : out_ext;
    int begin = g_rowptr[warp];
    int end   = g_rowptr[warp + 1];

    float4 acc = make_float4(0.f, 0.f, 0.f, 0.f);
    int i = begin;
    for (; i + 1 < end; i += 2) {
        int   s0 = g_srcs[i],     s1 = g_srcs[i + 1];
        float w0 = g_scale[i],    w1 = g_scale[i + 1];
        float4 v0 = *reinterpret_cast<const float4*>(H + (size_t)s0 * D + lane * 4);
        float4 v1 = *reinterpret_cast<const float4*>(H + (size_t)s1 * D + lane * 4);
        acc.x += w0 * v0.x; acc.y += w0 * v0.y; acc.z += w0 * v0.z; acc.w += w0 * v0.w;
        acc.x += w1 * v1.x; acc.y += w1 * v1.y; acc.z += w1 * v1.z; acc.w += w1 * v1.w;
    }
    if (i < end) {
        int   s0 = g_srcs[i];
        float w0 = g_scale[i];
        float4 v0 = *reinterpret_cast<const float4*>(H + (size_t)s0 * D + lane * 4);
        acc.x += w0 * v0.x; acc.y += w0 * v0.y; acc.z += w0 * v0.z; acc.w += w0 * v0.w;
    }

    float4 b = *reinterpret_cast<const float4*>(bias + lane * 4);
    float4 r;
    r.x = acc.x + b.x; r.x = r.x > 0.f ? r.x : 0.f;
    r.y = acc.y + b.y; r.y = r.y > 0.f ? r.y : 0.f;
    r.z = acc.z + b.z; r.z = r.z > 0.f ? r.z : 0.f;
    r.w = acc.w + b.w; r.w = r.w > 0.f ? r.w : 0.f;
    *reinterpret_cast<float4*>(outp + (size_t)warp * D + lane * 4) = r;
}

// ---------------- launch ----------------
extern "C" void kernel_launch(void* const* d_in, const int* in_sizes, int n_in,
                              void* d_out, int out_size) {
    const float* x  = (const float*)d_in[0];
    const void*  ei = d_in[1];                 // int32 or int64, auto-detected
    const float* ea = (const float*)d_in[2];
    const float* W1 = (const float*)d_in[3];
    const float* b1 = (const float*)d_in[4];
    const float* W2 = (const float*)d_in[5];
    const float* b2 = (const float*)d_in[6];
    float* out = (float*)d_out;

    const int gemm_grid = N_NODES / 64;                 // 625, exact
    const int agg_grid  = (N_NODES * 32 + 255) / 256;   // 5000 blocks

    init_kernel<<<NB, 256>>>((const int*)ei);                       // 0
    count_kernel<<<(N_EDGES + 255) / 256, 256>>>(ei);               // 1
    bsum_kernel<<<NB, 256>>>();                                     // 2
    gemm_nt_kernel<<<gemm_grid, 256>>>(x, W1, 0);                   // 3  <- profiled slot
    bscan_kernel<<<1, 256>>>();                                     // 4
    rowptr_kernel<<<NB, 256>>>();                                   // 5
    fill_kernel<<<(N_EDGES + 255) / 256, 256>>>(ei, ea);            // 6
    agg_kernel<<<agg_grid, 256>>>(b1, out, 0);                      // 7
    gemm_nt_kernel<<<gemm_grid, 256>>>(x, W2, 1);                   // 8
    agg_kernel<<<agg_grid, 256>>>(b2, out, 1);                      // 9
}

// round 7
// speedup vs baseline: 1.2909x; 1.2909x over previous
#include <cuda_runtime.h>
#include <cuda_bf16.h>

#define N_NODES 40000
#define N_EDGES 640000
#define D 128
#define NB 157  // ceil(40000/256) scan blocks

// ---------------- scratch (device globals, referenced by symbol only) ----------------
__device__ float g_h[N_NODES * D];        // GEMM output (per layer)
__device__ float g_y[N_NODES * D];        // layer-1 output
__device__ int   g_deg[N_NODES];          // degree histogram (by dst)
__device__ int   g_rowptr[N_NODES + 1];   // CSR row pointers
__device__ int   g_cursor[N_NODES];       // fill cursors
__device__ int   g_srcs[N_EDGES];         // CSR: src node per slot
__device__ float g_scale[N_EDGES];        // CSR: 1/edge_attr per slot
__device__ int   g_is32;                  // 1 if edge_index is int32, 0 if int64
__device__ int   g_bsum[NB];              // per-block degree sums
__device__ int   g_boff[NB];              // exclusive block offsets

// ---------------- init: zero degree histogram + detect edge_index dtype ----------------
__global__ __launch_bounds__(256) void init_kernel(const int* __restrict__ ei32) {
    int i = blockIdx.x * 256 + threadIdx.x;
    if (i < N_NODES) g_deg[i] = 0;
    if (blockIdx.x == 0) {
        int nz = 0;
        for (int s = threadIdx.x; s < 4096; s += 256)
            nz |= (ei32[2 * s + 1] != 0);
        nz = __syncthreads_or(nz);
        if (threadIdx.x == 0) g_is32 = nz;
    }
}

__device__ __forceinline__ int load_idx(const void* ei, int pos) {
    if (g_is32) return ((const int*)ei)[pos];
    return (int)((const long long*)ei)[pos];
}

__global__ void count_kernel(const void* __restrict__ ei) {
    int e = blockIdx.x * blockDim.x + threadIdx.x;
    if (e >= N_EDGES) return;
    int dst = load_idx(ei, N_EDGES + e);
    if ((unsigned)dst < (unsigned)N_NODES) atomicAdd(&g_deg[dst], 1);
}

// ---- scan phase 1: per-block sums ----
__global__ __launch_bounds__(256) void bsum_kernel() {
    int i = blockIdx.x * 256 + threadIdx.x;
    int v = (i < N_NODES) ? g_deg[i] : 0;
#pragma unroll
    for (int off = 16; off > 0; off >>= 1)
        v += __shfl_down_sync(0xffffffffu, v, off);
    __shared__ int ws[8];
    int wid = threadIdx.x >> 5, lane = threadIdx.x & 31;
    if (lane == 0) ws[wid] = v;
    __syncthreads();
    if (threadIdx.x == 0) {
        int s = 0;
#pragma unroll
        for (int w = 0; w < 8; w++) s += ws[w];
        g_bsum[blockIdx.x] = s;
    }
}

// ---- scan phase 2: exclusive scan of NB block sums ----
__global__ __launch_bounds__(256) void bscan_kernel() {
    int t = threadIdx.x;
    int lane = t & 31, wid = t >> 5;
    int v = (t < NB) ? g_bsum[t] : 0;
    int orig = v;
#pragma unroll
    for (int off = 1; off < 32; off <<= 1) {
        int u = __shfl_up_sync(0xffffffffu, v, off);
        if (lane >= off) v += u;
    }
    __shared__ int wsum[8];
    if (lane == 31) wsum[wid] = v;
    __syncthreads();
    if (wid == 0) {
        int s = (lane < 8) ? wsum[lane] : 0;
#pragma unroll
        for (int off = 1; off < 8; off <<= 1) {
            int u = __shfl_up_sync(0xffffffffu, s, off);
            if (lane >= off) s += u;
        }
        if (lane < 8) wsum[lane] = s;
    }
    __syncthreads();
    int incl = v + (wid > 0 ? wsum[wid - 1] : 0);
    if (t < NB) g_boff[t] = incl - orig;
}

// ---- scan phase 3: intra-block exclusive scan + write rowptr/cursor ----
__global__ __launch_bounds__(256) void rowptr_kernel() {
    int i = blockIdx.x * 256 + threadIdx.x;
    int lane = threadIdx.x & 31, wid = threadIdx.x >> 5;
    int v = (i < N_NODES) ? g_deg[i] : 0;
    int orig = v;
#pragma unroll
    for (int off = 1; off < 32; off <<= 1) {
        int u = __shfl_up_sync(0xffffffffu, v, off);
        if (lane >= off) v += u;
    }
    __shared__ int wsum[8];
    if (lane == 31) wsum[wid] = v;
    __syncthreads();
    if (wid == 0) {
        int s = (lane < 8) ? wsum[lane] : 0;
#pragma unroll
        for (int off = 1; off < 8; off <<= 1) {
            int u = __shfl_up_sync(0xffffffffu, s, off);
            if (lane >= off) s += u;
        }
        if (lane < 8) wsum[lane] = s;
    }
    __syncthreads();
    int incl = v + (wid > 0 ? wsum[wid - 1] : 0);
    int excl = incl - orig + g_boff[blockIdx.x];
    if (i < N_NODES) {
        g_rowptr[i] = excl;
        g_cursor[i] = excl;
        if (i == N_NODES - 1) g_rowptr[N_NODES] = excl + orig;
    }
}

__global__ void fill_kernel(const void* __restrict__ ei,
                            const float* __restrict__ ea) {
    int e = blockIdx.x * blockDim.x + threadIdx.x;
    if (e >= N_EDGES) return;
    int src = load_idx(ei, e);
    int dst = load_idx(ei, N_EDGES + e);
    if ((unsigned)dst >= (unsigned)N_NODES) return;
    if ((unsigned)src >= (unsigned)N_NODES) return;
    int pos = atomicAdd(&g_cursor[dst], 1);
    g_srcs[pos]  = src;
    g_scale[pos] = 1.0f / ea[e];
}

// ---------------- GEMM v3: g_h = X @ W^T. FFMA2, R5 layout + double-buffered smem ----------------
// BM=128, BN=128, BK=16, 256 threads, 8x8 thread tile (col-paired acc), 2 CTAs/SM.
__global__ __launch_bounds__(256, 2) void gemm_nt_kernel(const float* __restrict__ x_ext,
                                                         const float* __restrict__ W,
                                                         int layer) {
    __shared__ __align__(16) float As[2][16][128];   // [buf][k][m]  8 KB each
    __shared__ __align__(16) float Bs[2][16][128];   // [buf][k][n]
    const float* X = (layer == 0) ? x_ext : (const float*)g_y;
    const int block_row = blockIdx.x * 128;          // 313 blocks
    const int tid = threadIdx.x;
    const int tx = tid & 15;   // cols tx*8 .. tx*8+7
    const int ty = tid >> 4;   // rows ty*8 .. ty*8+7

    // loader mapping: 128x16 tile, 512 float4; 2 per thread
    const int l_r0 = tid >> 2;            // rows l_r0 and l_r0+64
    const int l_c  = (tid & 3) * 4;       // k-cols l_c..l_c+3

    unsigned long long acc2[8][4];
#pragma unroll
    for (int i = 0; i < 8; i++)
#pragma unroll
        for (int j = 0; j < 4; j++) acc2[i][j] = 0ull;

    float4 aR[2], bR[2];

    // prologue: fetch tile 0
    {
        int gr0 = block_row + l_r0, gr1 = block_row + l_r0 + 64;
        aR[0] = (gr0 < N_NODES) ? *reinterpret_cast<const float4*>(X + (size_t)gr0 * D + l_c)
                                : make_float4(0.f, 0.f, 0.f, 0.f);
        aR[1] = (gr1 < N_NODES) ? *reinterpret_cast<const float4*>(X + (size_t)gr1 * D + l_c)
                                : make_float4(0.f, 0.f, 0.f, 0.f);
        bR[0] = *reinterpret_cast<const float4*>(W + (size_t)l_r0 * D + l_c);
        bR[1] = *reinterpret_cast<const float4*>(W + (size_t)(l_r0 + 64) * D + l_c);
        // store to buf 0 (transposed [k][m]/[k][n])
        As[0][l_c + 0][l_r0] = aR[0].x; As[0][l_c + 1][l_r0] = aR[0].y;
        As[0][l_c + 2][l_r0] = aR[0].z; As[0][l_c + 3][l_r0] = aR[0].w;
        As[0][l_c + 0][l_r0 + 64] = aR[1].x; As[0][l_c + 1][l_r0 + 64] = aR[1].y;
        As[0][l_c + 2][l_r0 + 64] = aR[1].z; As[0][l_c + 3][l_r0 + 64] = aR[1].w;
        Bs[0][l_c + 0][l_r0] = bR[0].x; Bs[0][l_c + 1][l_r0] = bR[0].y;
        Bs[0][l_c + 2][l_r0] = bR[0].z; Bs[0][l_c + 3][l_r0] = bR[0].w;
        Bs[0][l_c + 0][l_r0 + 64] = bR[1].x; Bs[0][l_c + 1][l_r0 + 64] = bR[1].y;
        Bs[0][l_c + 2][l_r0 + 64] = bR[1].z; Bs[0][l_c + 3][l_r0 + 64] = bR[1].w;
    }
    __syncthreads();

#pragma unroll
    for (int t = 0; t < 8; t++) {
        const int cur = t & 1;
        // prefetch tile t+1 into registers (latency hidden by compute below)
        if (t < 7) {
            int k0 = (t + 1) * 16;
            int gr0 = block_row + l_r0, gr1 = block_row + l_r0 + 64;
            aR[0] = (gr0 < N_NODES) ? *reinterpret_cast<const float4*>(X + (size_t)gr0 * D + k0 + l_c)
                                    : make_float4(0.f, 0.f, 0.f, 0.f);
            aR[1] = (gr1 < N_NODES) ? *reinterpret_cast<const float4*>(X + (size_t)gr1 * D + k0 + l_c)
                                    : make_float4(0.f, 0.f, 0.f, 0.f);
            bR[0] = *reinterpret_cast<const float4*>(W + (size_t)l_r0 * D + k0 + l_c);
            bR[1] = *reinterpret_cast<const float4*>(W + (size_t)(l_r0 + 64) * D + k0 + l_c);
        }

        // compute on buf cur
#pragma unroll
        for (int k = 0; k < 16; k++) {
            float4 af0 = *reinterpret_cast<const float4*>(&As[cur][k][ty * 8]);
            float4 af1 = *reinterpret_cast<const float4*>(&As[cur][k][ty * 8 + 4]);
            ulonglong2 bv0 = *reinterpret_cast<const ulonglong2*>(&Bs[cur][k][tx * 8]);
            ulonglong2 bv1 = *reinterpret_cast<const ulonglong2*>(&Bs[cur][k][tx * 8 + 4]);
            unsigned long long b2[4] = {bv0.x, bv0.y, bv1.x, bv1.y};
            unsigned long long a2[8];
            asm("mov.b64 %0, {%1, %1};" : "=l"(a2[0]) : "r"(__float_as_uint(af0.x)));
            asm("mov.b64 %0, {%1, %1};" : "=l"(a2[1]) : "r"(__float_as_uint(af0.y)));
            asm("mov.b64 %0, {%1, %1};" : "=l"(a2[2]) : "r"(__float_as_uint(af0.z)));
            asm("mov.b64 %0, {%1, %1};" : "=l"(a2[3]) : "r"(__float_as_uint(af0.w)));
            asm("mov.b64 %0, {%1, %1};" : "=l"(a2[4]) : "r"(__float_as_uint(af1.x)));
            asm("mov.b64 %0, {%1, %1};" : "=l"(a2[5]) : "r"(__float_as_uint(af1.y)));
            asm("mov.b64 %0, {%1, %1};" : "=l"(a2[6]) : "r"(__float_as_uint(af1.z)));
            asm("mov.b64 %0, {%1, %1};" : "=l"(a2[7]) : "r"(__float_as_uint(af1.w)));
#pragma unroll
            for (int i = 0; i < 8; i++)
#pragma unroll
                for (int j = 0; j < 4; j++)
                    asm("fma.rn.f32x2 %0, %1, %2, %0;" : "+l"(acc2[i][j]) : "l"(a2[i]), "l"(b2[j]));
        }

        // store prefetched tile to the other buffer, one sync per tile
        if (t < 7) {
            const int nxt = cur ^ 1;
            As[nxt][l_c + 0][l_r0] = aR[0].x; As[nxt][l_c + 1][l_r0] = aR[0].y;
            As[nxt][l_c + 2][l_r0] = aR[0].z; As[nxt][l_c + 3][l_r0] = aR[0].w;
            As[nxt][l_c + 0][l_r0 + 64] = aR[1].x; As[nxt][l_c + 1][l_r0 + 64] = aR[1].y;
            As[nxt][l_c + 2][l_r0 + 64] = aR[1].z; As[nxt][l_c + 3][l_r0 + 64] = aR[1].w;
            Bs[nxt][l_c + 0][l_r0] = bR[0].x; Bs[nxt][l_c + 1][l_r0] = bR[0].y;
            Bs[nxt][l_c + 2][l_r0] = bR[0].z; Bs[nxt][l_c + 3][l_r0] = bR[0].w;
            Bs[nxt][l_c + 0][l_r0 + 64] = bR[1].x; Bs[nxt][l_c + 1][l_r0 + 64] = bR[1].y;
            Bs[nxt][l_c + 2][l_r0 + 64] = bR[1].z; Bs[nxt][l_c + 3][l_r0 + 64] = bR[1].w;
            __syncthreads();
        }
    }

#pragma unroll
    for (int i = 0; i < 8; i++) {
        int gr = block_row + ty * 8 + i;
        if (gr < N_NODES) {
            float o[8];
#pragma unroll
            for (int j = 0; j < 4; j++) {
                unsigned int lo, hi;
                asm("mov.b64 {%0, %1}, %2;" : "=r"(lo), "=r"(hi) : "l"(acc2[i][j]));
                o[2 * j]     = __uint_as_float(lo);
                o[2 * j + 1] = __uint_as_float(hi);
            }
            float4* op = reinterpret_cast<float4*>((float*)g_h + (size_t)gr * D + tx * 8);
            op[0] = make_float4(o[0], o[1], o[2], o[3]);
            op[1] = make_float4(o[4], o[5], o[6], o[7]);
        }
    }
}

// ---------------- aggregate: dst[n] = relu( sum_{e in CSR[n]} g_h[src_e]*scale_e + bias ) ----------------
__global__ __launch_bounds__(256) void agg_kernel(const float* __restrict__ bias,
                                                  float* __restrict__ out_ext,
                                                  int layer) {
    int warp = (blockIdx.x * blockDim.x + threadIdx.x) >> 5;
    int lane = threadIdx.x & 31;
    if (warp >= N_NODES) return;
    const float* H = (const float*)g_h;
    float* outp = (layer == 0) ? (float*)g_y : out_ext;
    int begin = g_rowptr[warp];
    int end   = g_rowptr[warp + 1];

    float4 acc = make_float4(0.f, 0.f, 0.f, 0.f);
    int i = begin;
    for (; i + 1 < end; i += 2) {
        int   s0 = g_srcs[i],     s1 = g_srcs[i + 1];
        float w0 = g_scale[i],    w1 = g_scale[i + 1];
        float4 v0 = *reinterpret_cast<const float4*>(H + (size_t)s0 * D + lane * 4);
        float4 v1 = *reinterpret_cast<const float4*>(H + (size_t)s1 * D + lane * 4);
        acc.x += w0 * v0.x; acc.y += w0 * v0.y; acc.z += w0 * v0.z; acc.w += w0 * v0.w;
        acc.x += w1 * v1.x; acc.y += w1 * v1.y; acc.z += w1 * v1.z; acc.w += w1 * v1.w;
    }
    if (i < end) {
        int   s0 = g_srcs[i];
        float w0 = g_scale[i];
        float4 v0 = *reinterpret_cast<const float4*>(H + (size_t)s0 * D + lane * 4);
        acc.x += w0 * v0.x; acc.y += w0 * v0.y; acc.z += w0 * v0.z; acc.w += w0 * v0.w;
    }

    float4 b = *reinterpret_cast<const float4*>(bias + lane * 4);
    float4 r;
    r.x = acc.x + b.x; r.x = r.x > 0.f ? r.x : 0.f;
    r.y = acc.y + b.y; r.y = r.y > 0.f ? r.y : 0.f;
    r.z = acc.z + b.z; r.z = r.z > 0.f ? r.z : 0.f;
    r.w = acc.w + b.w; r.w = r.w > 0.f ? r.w : 0.f;
    *reinterpret_cast<float4*>(outp + (size_t)warp * D + lane * 4) = r;
}

// ---------------- launch ----------------
extern "C" void kernel_launch(void* const* d_in, const int* in_sizes, int n_in,
                              void* d_out, int out_size) {
    const float* x  = (const float*)d_in[0];
    const void*  ei = d_in[1];                 // int32 or int64, auto-detected
    const float* ea = (const float*)d_in[2];
    const float* W1 = (const float*)d_in[3];
    const float* b1 = (const float*)d_in[4];
    const float* W2 = (const float*)d_in[5];
    const float* b2 = (const float*)d_in[6];
    float* out = (float*)d_out;

    const int gemm_grid = (N_NODES + 127) / 128;        // 313
    const int agg_grid  = (N_NODES * 32 + 255) / 256;   // 5000 blocks

    init_kernel<<<NB, 256>>>((const int*)ei);                       // 0
    count_kernel<<<(N_EDGES + 255) / 256, 256>>>(ei);               // 1
    bsum_kernel<<<NB, 256>>>();                                     // 2
    gemm_nt_kernel<<<gemm_grid, 256>>>(x, W1, 0);                   // 3  <- profiled slot
    bscan_kernel<<<1, 256>>>();                                     // 4
    rowptr_kernel<<<NB, 256>>>();                                   // 5
    fill_kernel<<<(N_EDGES + 255) / 256, 256>>>(ei, ea);            // 6
    agg_kernel<<<agg_grid, 256>>>(b1, out, 0);                      // 7
    gemm_nt_kernel<<<gemm_grid, 256>>>(x, W2, 1);                   // 8
    agg_kernel<<<agg_grid, 256>>>(b2, out, 1);                      // 9
}

// round 9
// speedup vs baseline: 1.7511x; 1.3565x over previous
#include <cuda_runtime.h>
#include <cuda_bf16.h>
#include <cstdint>

#define N_NODES 40000
#define N_EDGES 640000
#define D 128
#define NB 157  // ceil(40000/256) scan blocks

// ---------------- scratch (device globals, referenced by symbol only) ----------------
__device__ float g_h[N_NODES * D];            // GEMM output (per layer), fp32
__device__ unsigned short g_xhi[N_NODES * D]; // bf16 split of x
__device__ unsigned short g_xlo[N_NODES * D];
__device__ unsigned short g_yhi[N_NODES * D]; // bf16 split of layer-1 output
__device__ unsigned short g_ylo[N_NODES * D];
__device__ unsigned short g_w1hi[D * D], g_w1lo[D * D];
__device__ unsigned short g_w2hi[D * D], g_w2lo[D * D];
__device__ int   g_deg[N_NODES];
__device__ int   g_rowptr[N_NODES + 1];
__device__ int   g_cursor[N_NODES];
__device__ int   g_srcs[N_EDGES];
__device__ float g_scale[N_EDGES];
__device__ int   g_is32;
__device__ int   g_bsum[NB];
__device__ int   g_boff[NB];

// ---------------- init: zero degree histogram + detect edge_index dtype ----------------
__global__ __launch_bounds__(256) void init_kernel(const int* __restrict__ ei32) {
    int i = blockIdx.x * 256 + threadIdx.x;
    if (i < N_NODES) g_deg[i] = 0;
    if (blockIdx.x == 0) {
        int nz = 0;
        for (int s = threadIdx.x; s < 4096; s += 256)
            nz |= (ei32[2 * s + 1] != 0);
        nz = __syncthreads_or(nz);
        if (threadIdx.x == 0) g_is32 = nz;
    }
}

__device__ __forceinline__ int load_idx(const void* ei, int pos) {
    if (g_is32) return ((const int*)ei)[pos];
    return (int)((const long long*)ei)[pos];
}

__global__ void count_kernel(const void* __restrict__ ei) {
    int e = blockIdx.x * blockDim.x + threadIdx.x;
    if (e >= N_EDGES) return;
    int dst = load_idx(ei, N_EDGES + e);
    if ((unsigned)dst < (unsigned)N_NODES) atomicAdd(&g_deg[dst], 1);
}

__global__ __launch_bounds__(256) void bsum_kernel() {
    int i = blockIdx.x * 256 + threadIdx.x;
    int v = (i < N_NODES) ? g_deg[i] : 0;
#pragma unroll
    for (int off = 16; off > 0; off >>= 1)
        v += __shfl_down_sync(0xffffffffu, v, off);
    __shared__ int ws[8];
    int wid = threadIdx.x >> 5, lane = threadIdx.x & 31;
    if (lane == 0) ws[wid] = v;
    __syncthreads();
    if (threadIdx.x == 0) {
        int s = 0;
#pragma unroll
        for (int w = 0; w < 8; w++) s += ws[w];
        g_bsum[blockIdx.x] = s;
    }
}

__global__ __launch_bounds__(256) void bscan_kernel() {
    int t = threadIdx.x;
    int lane = t & 31, wid = t >> 5;
    int v = (t < NB) ? g_bsum[t] : 0;
    int orig = v;
#pragma unroll
    for (int off = 1; off < 32; off <<= 1) {
        int u = __shfl_up_sync(0xffffffffu, v, off);
        if (lane >= off) v += u;
    }
    __shared__ int wsum[8];
    if (lane == 31) wsum[wid] = v;
    __syncthreads();
    if (wid == 0) {
        int s = (lane < 8) ? wsum[lane] : 0;
#pragma unroll
        for (int off = 1; off < 8; off <<= 1) {
            int u = __shfl_up_sync(0xffffffffu, s, off);
            if (lane >= off) s += u;
        }
        if (lane < 8) wsum[lane] = s;
    }
    __syncthreads();
    int incl = v + (wid > 0 ? wsum[wid - 1] : 0);
    if (t < NB) g_boff[t] = incl - orig;
}

__global__ __launch_bounds__(256) void rowptr_kernel() {
    int i = blockIdx.x * 256 + threadIdx.x;
    int lane = threadIdx.x & 31, wid = threadIdx.x >> 5;
    int v = (i < N_NODES) ? g_deg[i] : 0;
    int orig = v;
#pragma unroll
    for (int off = 1; off < 32; off <<= 1) {
        int u = __shfl_up_sync(0xffffffffu, v, off);
        if (lane >= off) v += u;
    }
    __shared__ int wsum[8];
    if (lane == 31) wsum[wid] = v;
    __syncthreads();
    if (wid == 0) {
        int s = (lane < 8) ? wsum[lane] : 0;
#pragma unroll
        for (int off = 1; off < 8; off <<= 1) {
            int u = __shfl_up_sync(0xffffffffu, s, off);
            if (lane >= off) s += u;
        }
        if (lane < 8) wsum[lane] = s;
    }
    __syncthreads();
    int incl = v + (wid > 0 ? wsum[wid - 1] : 0);
    int excl = incl - orig + g_boff[blockIdx.x];
    if (i < N_NODES) {
        g_rowptr[i] = excl;
        g_cursor[i] = excl;
        if (i == N_NODES - 1) g_rowptr[N_NODES] = excl + orig;
    }
}

__global__ void fill_kernel(const void* __restrict__ ei,
                            const float* __restrict__ ea) {
    int e = blockIdx.x * blockDim.x + threadIdx.x;
    if (e >= N_EDGES) return;
    int src = load_idx(ei, e);
    int dst = load_idx(ei, N_EDGES + e);
    if ((unsigned)dst >= (unsigned)N_NODES) return;
    if ((unsigned)src >= (unsigned)N_NODES) return;
    int pos = atomicAdd(&g_cursor[dst], 1);
    g_srcs[pos]  = src;
    g_scale[pos] = 1.0f / ea[e];
}

// ---------------- f32 -> bf16 hi/lo split converters ----------------
__device__ __forceinline__ void split_bf16(float f, unsigned short& hi, unsigned short& lo) {
    __nv_bfloat16 h = __float2bfloat16(f);
    float r = f - __bfloat162float(h);
    hi = __bfloat16_as_ushort(h);
    lo = __bfloat16_as_ushort(__float2bfloat16(r));
}

__global__ __launch_bounds__(256) void conv_x_kernel(const float* __restrict__ x) {
    int i = blockIdx.x * 256 + threadIdx.x;      // float4 index
    if (i * 4 >= N_NODES * D) return;
    float4 v = reinterpret_cast<const float4*>(x)[i];
    ushort4 hi, lo;
    split_bf16(v.x, hi.x, lo.x); split_bf16(v.y, hi.y, lo.y);
    split_bf16(v.z, hi.z, lo.z); split_bf16(v.w, hi.w, lo.w);
    reinterpret_cast<ushort4*>(g_xhi)[i] = hi;
    reinterpret_cast<ushort4*>(g_xlo)[i] = lo;
}

__global__ __launch_bounds__(256) void conv_w_kernel(const float* __restrict__ W1,
                                                     const float* __restrict__ W2) {
    int i = blockIdx.x * 256 + threadIdx.x;      // 0..8191 (two 4096 float4 sets)
    if (i >= 8192) return;
    const float* src = (i < 4096) ? W1 : W2;
    unsigned short* dh = (i < 4096) ? g_w1hi : g_w2hi;
    unsigned short* dl = (i < 4096) ? g_w1lo : g_w2lo;
    int j = i & 4095;
    float4 v = reinterpret_cast<const float4*>(src)[j];
    ushort4 hi, lo;
    split_bf16(v.x, hi.x, lo.x); split_bf16(v.y, hi.y, lo.y);
    split_bf16(v.z, hi.z, lo.z); split_bf16(v.w, hi.w, lo.w);
    reinterpret_cast<ushort4*>(dh)[j] = hi;
    reinterpret_cast<ushort4*>(dl)[j] = lo;
}

// ---------------- tensor-core GEMM via mma.sync (HMMA bf16, 3-term split) ----------------
// CTA: 128x128 tile, 8 warps (4 m-groups x 2 n-groups), warp tile 32x64.
// K=128 in two 64-chunks. smem: 4 tiles [128][72] bf16 (padded, conflict-free ldmatrix).
#define SP 72                        // padded row stride (bf16 elems)
#define TILE_B (128 * SP * 2)        // bytes per tile = 18432
#define OFF_AHI 0
#define OFF_ALO (TILE_B)
#define OFF_BHI (2 * TILE_B)
#define OFF_BLO (3 * TILE_B)
#define GEMM_SMEM (4 * TILE_B)       // 73728

__device__ __forceinline__ void ldsm4(uint32_t* r, uint32_t addr) {
    asm volatile("ldmatrix.sync.aligned.m8n8.x4.shared.b16 {%0,%1,%2,%3}, [%4];"
                 : "=r"(r[0]), "=r"(r[1]), "=r"(r[2]), "=r"(r[3]) : "r"(addr));
}
__device__ __forceinline__ void mma16816(float* d, const uint32_t* a, uint32_t b0, uint32_t b1) {
    asm volatile(
        "mma.sync.aligned.m16n8k16.row.col.f32.bf16.bf16.f32 "
        "{%0,%1,%2,%3}, {%4,%5,%6,%7}, {%8,%9}, {%0,%1,%2,%3};"
        : "+f"(d[0]), "+f"(d[1]), "+f"(d[2]), "+f"(d[3])
        : "r"(a[0]), "r"(a[1]), "r"(a[2]), "r"(a[3]), "r"(b0), "r"(b1));
}

__global__ __launch_bounds__(256, 2) void gemm_mma_kernel(int layer) {
    extern __shared__ char smem[];
    uint32_t sb;
    asm("{ .reg .u64 t; cvta.to.shared.u64 t, %1; cvt.u32.u64 %0, t; }" : "=r"(sb) : "l"(smem));
    const int tid  = threadIdx.x;
    const int wid  = tid >> 5;
    const int lane = tid & 31;
    const int lane8 = lane & 7;
    const int g     = lane >> 3;
    const int m0 = (wid & 3) * 32;
    const int n0 = (wid >> 2) * 64;
    const int block_row = blockIdx.x * 128;

    const unsigned short* Ah = (layer == 0) ? g_xhi : g_yhi;
    const unsigned short* Al = (layer == 0) ? g_xlo : g_ylo;
    const unsigned short* Bh = (layer == 0) ? g_w1hi : g_w2hi;
    const unsigned short* Bl = (layer == 0) ? g_w1lo : g_w2lo;

    float acc[2][8][4];
#pragma unroll
    for (int i = 0; i < 2; i++)
#pragma unroll
        for (int j = 0; j < 8; j++)
#pragma unroll
            for (int c = 0; c < 4; c++) acc[i][j][c] = 0.0f;

    // loader mapping: 1024 uint4 per tile; 4 per thread
    const int l_r = tid >> 3;            // base rows tid/8 + 32*it
    const int l_c = (tid & 7) * 8;       // bf16 col group

#pragma unroll
    for (int chunk = 0; chunk < 2; chunk++) {
        const int kb = chunk * 64;
        if (chunk) __syncthreads();   // protect previous tiles before overwrite
        // load A hi/lo (guarded) and B hi/lo
#pragma unroll
        for (int it = 0; it < 4; it++) {
            int r = l_r + it * 32;
            int gr = block_row + r;
            uint4 vh = make_uint4(0u, 0u, 0u, 0u), vl = vh;
            if (gr < N_NODES) {
                vh = *reinterpret_cast<const uint4*>(Ah + (size_t)gr * D + kb + l_c);
                vl = *reinterpret_cast<const uint4*>(Al + (size_t)gr * D + kb + l_c);
            }
            int so = (r * SP + l_c) * 2;
            *reinterpret_cast<uint4*>(smem + OFF_AHI + so) = vh;
            *reinterpret_cast<uint4*>(smem + OFF_ALO + so) = vl;
            uint4 wh = *reinterpret_cast<const uint4*>(Bh + (size_t)r * D + kb + l_c);
            uint4 wl = *reinterpret_cast<const uint4*>(Bl + (size_t)r * D + kb + l_c);
            *reinterpret_cast<uint4*>(smem + OFF_BHI + so) = wh;
            *reinterpret_cast<uint4*>(smem + OFF_BLO + so) = wl;
        }
        __syncthreads();

#pragma unroll
        for (int k16 = 0; k16 < 4; k16++) {
            const int k0 = k16 * 16;
            uint32_t ahi[2][4], alo[2][4];
#pragma unroll
            for (int mi = 0; mi < 2; mi++) {
                int arow = m0 + mi * 16 + ((g & 1) << 3) + lane8;
                int acol = k0 + ((g >> 1) << 3);
                uint32_t ao = (uint32_t)(arow * SP + acol) * 2;
                ldsm4(ahi[mi], sb + OFF_AHI + ao);
                ldsm4(alo[mi], sb + OFF_ALO + ao);
            }
#pragma unroll
            for (int jj = 0; jj < 4; jj++) {
                int brow = n0 + jj * 16 + ((g >> 1) << 3) + lane8;
                int bcol = k0 + ((g & 1) << 3);
                uint32_t bo = (uint32_t)(brow * SP + bcol) * 2;
                uint32_t bh[4], bl[4];
                ldsm4(bh, sb + OFF_BHI + bo);
                ldsm4(bl, sb + OFF_BLO + bo);
#pragma unroll
                for (int f = 0; f < 2; f++) {
                    uint32_t bh0 = bh[2 * f], bh1 = bh[2 * f + 1];
                    uint32_t bl0 = bl[2 * f], bl1 = bl[2 * f + 1];
#pragma unroll
                    for (int mi = 0; mi < 2; mi++) {
                        float* d = acc[mi][jj * 2 + f];
                        mma16816(d, ahi[mi], bh0, bh1);   // hi*hi
                        mma16816(d, ahi[mi], bl0, bl1);   // hi*lo
                        mma16816(d, alo[mi], bh0, bh1);   // lo*hi
                    }
                }
            }
        }
    }

    // epilogue: write fp32 to g_h
#pragma unroll
    for (int mi = 0; mi < 2; mi++) {
#pragma unroll
        for (int j = 0; j < 8; j++) {
            int row = block_row + m0 + mi * 16 + (lane >> 2);
            int col = n0 + j * 8 + (lane & 3) * 2;
            float* d = acc[mi][j];
            if (row < N_NODES)
                *reinterpret_cast<float2*>((float*)g_h + (size_t)row * D + col) = make_float2(d[0], d[1]);
            if (row + 8 < N_NODES)
                *reinterpret_cast<float2*>((float*)g_h + (size_t)(row + 8) * D + col) = make_float2(d[2], d[3]);
        }
    }
}

// ---------------- aggregate: relu( sum_{e in CSR[n]} g_h[src_e]*scale_e + bias ) ----------------
// layer 0 -> writes bf16 hi/lo split (g_yhi/g_ylo); layer 1 -> writes fp32 out_ext.
__global__ __launch_bounds__(256) void agg_kernel(const float* __restrict__ bias,
                                                  float* __restrict__ out_ext,
                                                  int layer) {
    int warp = (blockIdx.x * blockDim.x + threadIdx.x) >> 5;
    int lane = threadIdx.x & 31;
    if (warp >= N_NODES) return;
    const float* H = (const float*)g_h;
    int begin = g_rowptr[warp];
    int end   = g_rowptr[warp + 1];

    float4 acc = make_float4(0.f, 0.f, 0.f, 0.f);
    int i = begin;
    for (; i + 1 < end; i += 2) {
        int   s0 = g_srcs[i],     s1 = g_srcs[i + 1];
        float w0 = g_scale[i],    w1 = g_scale[i + 1];
        float4 v0 = *reinterpret_cast<const float4*>(H + (size_t)s0 * D + lane * 4);
        float4 v1 = *reinterpret_cast<const float4*>(H + (size_t)s1 * D + lane * 4);
        acc.x += w0 * v0.x; acc.y += w0 * v0.y; acc.z += w0 * v0.z; acc.w += w0 * v0.w;
        acc.x += w1 * v1.x; acc.y += w1 * v1.y; acc.z += w1 * v1.z; acc.w += w1 * v1.w;
    }
    if (i < end) {
        int   s0 = g_srcs[i];
        float w0 = g_scale[i];
        float4 v0 = *reinterpret_cast<const float4*>(H + (size_t)s0 * D + lane * 4);
        acc.x += w0 * v0.x; acc.y += w0 * v0.y; acc.z += w0 * v0.z; acc.w += w0 * v0.w;
    }

    float4 b = *reinterpret_cast<const float4*>(bias + lane * 4);
    float4 r;
    r.x = acc.x + b.x; r.x = r.x > 0.f ? r.x : 0.f;
    r.y = acc.y + b.y; r.y = r.y > 0.f ? r.y : 0.f;
    r.z = acc.z + b.z; r.z = r.z > 0.f ? r.z : 0.f;
    r.w = acc.w + b.w; r.w = r.w > 0.f ? r.w : 0.f;

    if (layer == 1) {
        *reinterpret_cast<float4*>(out_ext + (size_t)warp * D + lane * 4) = r;
    } else {
        ushort4 hi, lo;
        split_bf16(r.x, hi.x, lo.x); split_bf16(r.y, hi.y, lo.y);
        split_bf16(r.z, hi.z, lo.z); split_bf16(r.w, hi.w, lo.w);
        size_t idx = ((size_t)warp * D + lane * 4) >> 2;
        reinterpret_cast<ushort4*>(g_yhi)[idx] = hi;
        reinterpret_cast<ushort4*>(g_ylo)[idx] = lo;
    }
}

// ---------------- launch ----------------
extern "C" void kernel_launch(void* const* d_in, const int* in_sizes, int n_in,
                              void* d_out, int out_size) {
    const float* x  = (const float*)d_in[0];
    const void*  ei = d_in[1];                 // int32 or int64, auto-detected
    const float* ea = (const float*)d_in[2];
    const float* W1 = (const float*)d_in[3];
    const float* b1 = (const float*)d_in[4];
    const float* W2 = (const float*)d_in[5];
    const float* b2 = (const float*)d_in[6];
    float* out = (float*)d_out;

    cudaFuncSetAttribute(gemm_mma_kernel, cudaFuncAttributeMaxDynamicSharedMemorySize, GEMM_SMEM);

    const int gemm_grid = (N_NODES + 127) / 128;        // 313
    const int agg_grid  = (N_NODES * 32 + 255) / 256;   // 5000 blocks
    const int convx_grid = (N_NODES * D / 4 + 255) / 256;

    init_kernel<<<NB, 256>>>((const int*)ei);                         // 0
    conv_x_kernel<<<convx_grid, 256>>>(x);                            // 1
    conv_w_kernel<<<32, 256>>>(W1, W2);                               // 2
    gemm_mma_kernel<<<gemm_grid, 256, GEMM_SMEM>>>(0);                // 3  <- profiled slot
    count_kernel<<<(N_EDGES + 255) / 256, 256>>>(ei);                 // 4
    bsum_kernel<<<NB, 256>>>();                                       // 5
    bscan_kernel<<<1, 256>>>();                                       // 6
    rowptr_kernel<<<NB, 256>>>();                                     // 7
    fill_kernel<<<(N_EDGES + 255) / 256, 256>>>(ei, ea);              // 8
    agg_kernel<<<agg_grid, 256>>>(b1, out, 0);                        // 9
    gemm_mma_kernel<<<gemm_grid, 256, GEMM_SMEM>>>(1);                // 10
    agg_kernel<<<agg_grid, 256>>>(b2, out, 1);                        // 11
}